// round 11
// baseline (speedup 1.0000x reference)
#include <cuda_runtime.h>
#include <cuda_fp16.h>
#include <cstdint>

#define SEQ 2048
#define DM 1024
#define NH 16
#define HD 64
#define NANCH 3
#define QPB 4

// ---------------- scratch ------------------------------------------------------
__device__ __half g_qh16[SEQ * DM];          // Q after RoPE, fp16 [S, H*D]
__device__ __half g_khh[NH * SEQ * HD];      // K after RoPE, fp16 [H,S,D] (128B rows)
__device__ __half g_vhh[NH * SEQ * HD];      // V fp16 [H,S,D] (128B rows)
__device__ __half g_xh[SEQ * DM];            // x fp16
__device__ __half g_wth[3072 * DM];          // [n,k] Wq|Wk|Wv^T fp16
__device__ __half g_woth[DM * DM];           // [n,k] Wo^T fp16
__device__ __half g_ath[SEQ * DM];           // attn out fp16 [S, H*D]

// ---------------- PTX helpers --------------------------------------------------
__device__ __forceinline__ uint32_t smem_u32(const void* p) {
    uint32_t a;
    asm("{ .reg .u64 t; cvta.to.shared.u64 t, %1; cvt.u32.u64 %0, t; }" : "=r"(a) : "l"(p));
    return a;
}
__device__ __forceinline__ void cp16(uint32_t s, const void* g) {
    asm volatile("cp.async.cg.shared.global [%0], [%1], 16;" :: "r"(s), "l"(g));
}
#define CP_COMMIT() asm volatile("cp.async.commit_group;" ::: "memory")
#define CP_WAIT1()  asm volatile("cp.async.wait_group 1;" ::: "memory")
#define CP_WAIT0()  asm volatile("cp.async.wait_group 0;" ::: "memory")

__device__ __forceinline__ void ldsm_x4(uint32_t& r0, uint32_t& r1, uint32_t& r2,
                                        uint32_t& r3, uint32_t a) {
    asm volatile("ldmatrix.sync.aligned.m8n8.x4.shared.b16 {%0,%1,%2,%3}, [%4];"
                 : "=r"(r0), "=r"(r1), "=r"(r2), "=r"(r3) : "r"(a));
}
__device__ __forceinline__ void mma_f16(float* d, const uint32_t* a, const uint32_t* b) {
    asm volatile(
        "mma.sync.aligned.m16n8k16.row.col.f32.f16.f16.f32 "
        "{%0,%1,%2,%3}, {%4,%5,%6,%7}, {%8,%9}, {%0,%1,%2,%3};"
        : "+f"(d[0]), "+f"(d[1]), "+f"(d[2]), "+f"(d[3])
        : "r"(a[0]), "r"(a[1]), "r"(a[2]), "r"(a[3]), "r"(b[0]), "r"(b[1]));
}

// ---------------- prep -----------------------------------------------------------
__global__ void split_x(const float* __restrict__ x) {
    int i = blockIdx.x * 256 + threadIdx.x;
    g_xh[i] = __float2half(x[i]);
}

// W [k][n] -> Wt [n][k] fp16. z 0..2 -> Wq/Wk/Wv; z==3 -> Wo
__global__ void transpose_w(const float* __restrict__ Wq, const float* __restrict__ Wk,
                            const float* __restrict__ Wv, const float* __restrict__ Wo) {
    __shared__ float tile[32][33];
    int z = blockIdx.z;
    const float* W = (z == 0) ? Wq : (z == 1) ? Wk : (z == 2) ? Wv : Wo;
    __half* dst = (z < 3) ? (g_wth + (size_t)z * DM * DM) : g_woth;
    int k0 = blockIdx.y * 32, n0 = blockIdx.x * 32;
    int tx = threadIdx.x, ty = threadIdx.y;
    tile[ty][tx] = W[(size_t)(k0 + ty) * DM + n0 + tx];
    __syncthreads();
    dst[(size_t)(n0 + ty) * DM + k0 + tx] = __float2half(tile[tx][ty]);
}

// ---------------- fp16 GEMM: C[M,N] = A[M,K] @ B[N,K]^T --------------------------
#define F_BK 64
#define F_STG 32768
#define F_OFF_B 16384
#define F_NSTAGE 3

__device__ __forceinline__ uint32_t swz8(uint32_t row, uint32_t seg) {
    return row * 128 + ((seg ^ (row & 7)) << 4);
}

__device__ __forceinline__ void f16_load_chunk(
    uint32_t stage, int tid, int c, int m0, int n0, int K,
    const __half* A, const __half* B)
{
    #pragma unroll
    for (int mtx = 0; mtx < 2; mtx++) {
        const int r0 = (mtx == 0) ? m0 : n0;
        const __half* src = (mtx == 0) ? A : B;
        const uint32_t off = mtx ? F_OFF_B : 0;
        #pragma unroll
        for (int i = 0; i < 4; i++) {
            int lin = i * 256 + tid;
            int row = lin >> 3, seg = lin & 7;
            const void* g = src + (size_t)(r0 + row) * K + c * F_BK + seg * 8;
            cp16(stage + off + swz8(row, seg), g);
        }
    }
}

__global__ void __launch_bounds__(256) gemm_f16(
    const __half* __restrict__ A, const __half* __restrict__ B,
    float* __restrict__ C, int Nstride, int K, int mode,
    __half* __restrict__ Qout, __half* __restrict__ Kout, __half* __restrict__ Vout,
    const float* __restrict__ cosT, const float* __restrict__ sinT)
{
    extern __shared__ __align__(1024) char dsm[];
    const uint32_t tiles = smem_u32(dsm);

    const int tid = threadIdx.x;
    const int m0 = blockIdx.y * 128, n0 = blockIdx.x * 128;
    const int nCh = K / F_BK;

    const int w = tid >> 5, lane = tid & 31;
    const int wm = (w & 3) * 32;
    const int wn = (w >> 2) * 64;

    float acc[2][8][4];
    #pragma unroll
    for (int i = 0; i < 2; i++)
        #pragma unroll
        for (int j = 0; j < 8; j++)
            #pragma unroll
            for (int e = 0; e < 4; e++) acc[i][j][e] = 0.f;

    f16_load_chunk(tiles, tid, 0, m0, n0, K, A, B); CP_COMMIT();
    f16_load_chunk(tiles + F_STG, tid, 1, m0, n0, K, A, B); CP_COMMIT();

    const int aRowL = lane & 15;
    const int aSegL = lane >> 4;
    const int bRowL = ((lane >> 4) & 1) * 8 + (lane & 7);
    const int bSegL = (lane >> 3) & 1;

    for (int c = 0; c < nCh; c++) {
        const uint32_t buf = tiles + (c % F_NSTAGE) * F_STG;
        CP_WAIT1();
        __syncthreads();
        if (c + 2 < nCh)
            f16_load_chunk(tiles + ((c + 2) % F_NSTAGE) * F_STG, tid, c + 2, m0, n0, K, A, B);
        CP_COMMIT();

        #pragma unroll
        for (int k16 = 0; k16 < 4; k16++) {
            uint32_t af[2][4], bf[4][4];
            #pragma unroll
            for (int mt = 0; mt < 2; mt++) {
                uint32_t row = wm + mt * 16 + aRowL;
                ldsm_x4(af[mt][0], af[mt][1], af[mt][2], af[mt][3],
                        buf + swz8(row, k16 * 2 + aSegL));
            }
            #pragma unroll
            for (int np = 0; np < 4; np++) {
                uint32_t row = wn + np * 16 + bRowL;
                ldsm_x4(bf[np][0], bf[np][1], bf[np][2], bf[np][3],
                        buf + F_OFF_B + swz8(row, k16 * 2 + bSegL));
            }
            #pragma unroll
            for (int mt = 0; mt < 2; mt++)
                #pragma unroll
                for (int np = 0; np < 4; np++)
                    #pragma unroll
                    for (int h = 0; h < 2; h++)
                        mma_f16(acc[mt][np * 2 + h], af[mt], &bf[np][h * 2]);
        }
        __syncthreads();
    }

    const int erow = lane >> 2, ecol = (lane & 3) * 2;

    if (mode == 0) {
        const int ncol = n0 + wn;
        const int zsel = ncol >> 10;
        const int hh = (ncol >> 6) & 15;
        #pragma unroll
        for (int mt = 0; mt < 2; mt++) {
            #pragma unroll
            for (int rsel = 0; rsel < 2; rsel++) {
                const int s = m0 + wm + mt * 16 + erow + rsel * 8;
                if (zsel == 2) {
                    __half* vb = Vout + ((size_t)hh * SEQ + s) * HD;
                    #pragma unroll
                    for (int nt = 0; nt < 8; nt++)
                        *(__half2*)(vb + nt * 8 + ecol) =
                            __floats2half2_rn(acc[mt][nt][rsel * 2], acc[mt][nt][rsel * 2 + 1]);
                } else {
                    __half* ob = (zsel == 0) ? (Qout + (size_t)s * DM + hh * HD)
                                             : (Kout + ((size_t)hh * SEQ + s) * HD);
                    #pragma unroll
                    for (int nt = 0; nt < 4; nt++) {
                        const int d0 = nt * 8 + ecol;
                        const float c0 = cosT[s * 32 + d0],     sn0 = sinT[s * 32 + d0];
                        const float c1 = cosT[s * 32 + d0 + 1], sn1 = sinT[s * 32 + d0 + 1];
                        const float a0 = acc[mt][nt][rsel * 2],     a1 = acc[mt][nt][rsel * 2 + 1];
                        const float b0 = acc[mt][nt + 4][rsel * 2], b1 = acc[mt][nt + 4][rsel * 2 + 1];
                        *(__half2*)(ob + d0) =
                            __floats2half2_rn(a0 * c0 - b0 * sn0, a1 * c1 - b1 * sn1);
                        *(__half2*)(ob + d0 + 32) =
                            __floats2half2_rn(b0 * c0 + a0 * sn0, b1 * c1 + a1 * sn1);
                    }
                }
            }
        }
    } else {
        #pragma unroll
        for (int mt = 0; mt < 2; mt++)
            #pragma unroll
            for (int nt = 0; nt < 8; nt++) {
                const float* d = acc[mt][nt];
                size_t r = (size_t)(m0 + wm + mt * 16 + erow);
                size_t col = n0 + wn + nt * 8 + ecol;
                *(float2*)&C[r * Nstride + col]       = make_float2(d[0], d[1]);
                *(float2*)&C[(r + 8) * Nstride + col] = make_float2(d[2], d[3]);
            }
    }
}

// ---------------- sparse attention: 4 queries / 256-thread block ----------------
// Logits via mma.sync (K smem tiles, q replicated across B columns).
__global__ void __launch_bounds__(256) attn(const int* __restrict__ anchors) {
    const int h = blockIdx.y;
    const int tid = threadIdx.x;
    const int ql = tid >> 6;
    const int j = tid & 63;
    const int s = blockIdx.x * QPB + ql;
    const int wq = (tid >> 5) & 1;           // warp within query
    const int lane = tid & 31;

    __shared__ __align__(16) char sK[QPB][4 * 2048];   // 4 tiles x 16 rows x 128B
    __shared__ __half2 sqh[QPB][32];                   // q as half2
    __shared__ float2 sWO[QPB][64];                    // (weight, byteoff-as-float)
    __shared__ int stile[QPB][4];
    __shared__ float wred[QPB][2][2];
    __shared__ float spart[QPB][2][64];

    // q (half2) and tile indices
    if (j < 32)
        sqh[ql][j] = ((const __half2*)(g_qh16 + (size_t)s * DM + h * HD))[j];
    if (j < 4)
        stile[ql][j] = (j < NANCH) ? anchors[(h * SEQ + s) * NANCH + j] : (s >> 4);
    __syncthreads();

    // stage 4 K tiles (2KB each, contiguous in gmem) coalesced into smem
    {
        const uint32_t sbase = smem_u32(sK[ql]);
        #pragma unroll
        for (int i = 0; i < 8; i++) {
            const int chunk = i * 64 + j;          // 0..511
            const int tile = chunk >> 7;
            const int c = chunk & 127;             // 16B chunk within tile
            const int r = c >> 3, seg = c & 7;
            const char* g = (const char*)(g_khh + ((size_t)h * SEQ + stile[ql][tile] * 16) * HD)
                            + c * 16;
            cp16(sbase + tile * 2048 + r * 128 + ((seg ^ (r & 7)) << 4), g);
        }
    }
    CP_COMMIT();
    CP_WAIT0();
    __syncthreads();

    // B fragments: q replicated across all 8 n-columns
    uint32_t bq[4][2];
    #pragma unroll
    for (int c = 0; c < 4; c++) {
        bq[c][0] = *(const uint32_t*)&sqh[ql][c * 8 + (lane & 3)];
        bq[c][1] = *(const uint32_t*)&sqh[ql][c * 8 + (lane & 3) + 4];
    }

    // logits via mma: 2 m-tiles of 16 keys, 4 k-chunks each
    const uint32_t sKb = smem_u32(sK[ql]);
    float lg[4];                             // keys: wq*32 + {r, r+8, 16+r, 24+r}
    #pragma unroll
    for (int t = 0; t < 2; t++) {
        float c4[4] = {0.f, 0.f, 0.f, 0.f};
        #pragma unroll
        for (int c = 0; c < 4; c++) {
            uint32_t a[4];
            ldsm_x4(a[0], a[1], a[2], a[3],
                    sKb + swz8(wq * 32 + t * 16 + (lane & 15), c * 2 + (lane >> 4)));
            mma_f16(c4, a, bq[c]);
        }
        lg[t * 2]     = c4[0] * 0.125f;      // key row r
        lg[t * 2 + 1] = c4[2] * 0.125f;      // key row r+8
    }

    const int r = lane >> 2;
    const int ti0 = stile[ql][2 * wq], ti1 = stile[ql][2 * wq + 1];
    int kid[4] = {ti0 * 16 + r, ti0 * 16 + r + 8, ti1 * 16 + r, ti1 * 16 + r + 8};
    bool msk[4];
    #pragma unroll
    for (int i = 0; i < 4; i++) {
        msk[i] = kid[i] > s;
        if (msk[i]) lg[i] = -1e30f;
    }

    // softmax (each key duplicated x4 across the quad -> sum scaled by 0.25)
    float m = fmaxf(fmaxf(lg[0], lg[1]), fmaxf(lg[2], lg[3]));
    #pragma unroll
    for (int off = 16; off; off >>= 1) m = fmaxf(m, __shfl_xor_sync(~0u, m, off));
    if (lane == 0) wred[ql][0][wq] = m;
    __syncthreads();
    m = fmaxf(wred[ql][0][0], wred[ql][0][1]);

    float e[4];
    float lsum = 0.f;
    #pragma unroll
    for (int i = 0; i < 4; i++) {
        e[i] = msk[i] ? 0.f : __expf(lg[i] - m);
        lsum += e[i];
    }
    #pragma unroll
    for (int off = 16; off; off >>= 1) lsum += __shfl_xor_sync(~0u, lsum, off);
    if (lane == 0) wred[ql][1][wq] = lsum;
    __syncthreads();
    const float ssum = (wred[ql][1][0] + wred[ql][1][1]) * 0.25f;
    const float inv = 1.0f / ssum;

    // quad leaders publish (weight, V byte offset) for their 4 keys
    if ((lane & 3) == 0) {
        sWO[ql][wq * 32 + r]      = make_float2(e[0] * inv, __int_as_float(kid[0] << 7));
        sWO[ql][wq * 32 + r + 8]  = make_float2(e[1] * inv, __int_as_float(kid[1] << 7));
        sWO[ql][wq * 32 + r + 16] = make_float2(e[2] * inv, __int_as_float(kid[2] << 7));
        sWO[ql][wq * 32 + r + 24] = make_float2(e[3] * inv, __int_as_float(kid[3] << 7));
    }
    __syncwarp();

    // V phase: 2 keys per iteration; lanes 0-15 even key, 16-31 odd key.
    // Each lane loads 8B (4 halves = dims 4*(lane&15)..+3) -> full 128B line per key.
    {
        const char* vb = (const char*)g_vhh + (size_t)h * SEQ * 128 + 8 * (lane & 15);
        const int sel = lane >> 4;           // 0 or 1
        float4 acc = make_float4(0.f, 0.f, 0.f, 0.f);
        #pragma unroll
        for (int i = 0; i < 16; i++) {
            const float2 wo = sWO[ql][wq * 32 + 2 * i + sel];
            const float wgt = wo.x;
            const __half2* vp = (const __half2*)(vb + __float_as_int(wo.y));
            const float2 v0 = __half22float2(vp[0]);
            const float2 v1 = __half22float2(vp[1]);
            acc.x = fmaf(wgt, v0.x, acc.x);
            acc.y = fmaf(wgt, v0.y, acc.y);
            acc.z = fmaf(wgt, v1.x, acc.z);
            acc.w = fmaf(wgt, v1.y, acc.w);
        }
        // combine even/odd halves (lanes l and l^16 hold same dims)
        acc.x += __shfl_xor_sync(~0u, acc.x, 16);
        acc.y += __shfl_xor_sync(~0u, acc.y, 16);
        acc.z += __shfl_xor_sync(~0u, acc.z, 16);
        acc.w += __shfl_xor_sync(~0u, acc.w, 16);
        if (lane < 16)
            ((float4*)spart[ql][wq])[lane] = acc;
    }
    __syncthreads();

    g_ath[(size_t)s * DM + h * HD + j] =
        __float2half(spart[ql][0][j] + spart[ql][1][j]);
}

// ---------------- launch ---------------------------------------------------------
extern "C" void kernel_launch(void* const* d_in, const int* in_sizes, int n_in,
                              void* d_out, int out_size)
{
    const float* x    = (const float*)d_in[0];
    const float* Wq   = (const float*)d_in[1];
    const float* Wk   = (const float*)d_in[2];
    const float* Wv   = (const float*)d_in[3];
    const float* Wo   = (const float*)d_in[4];
    const float* cosT = (const float*)d_in[5];
    const float* sinT = (const float*)d_in[6];
    const int* anchors = (const int*)d_in[7];
    float* out = (float*)d_out;

    const int SMEM_F = F_NSTAGE * F_STG;   // 96 KB
    cudaFuncSetAttribute(gemm_f16, cudaFuncAttributeMaxDynamicSharedMemorySize, SMEM_F);

    __half *xh = nullptr, *wth = nullptr, *woth = nullptr, *ath = nullptr;
    __half *qh = nullptr, *kh = nullptr, *vh = nullptr;
    cudaGetSymbolAddress((void**)&xh, g_xh);
    cudaGetSymbolAddress((void**)&wth, g_wth);
    cudaGetSymbolAddress((void**)&woth, g_woth);
    cudaGetSymbolAddress((void**)&ath, g_ath);
    cudaGetSymbolAddress((void**)&qh, g_qh16);
    cudaGetSymbolAddress((void**)&kh, g_khh);
    cudaGetSymbolAddress((void**)&vh, g_vhh);

    split_x<<<(SEQ * DM) / 256, 256>>>(x);
    transpose_w<<<dim3(32, 32, 4), dim3(32, 32)>>>(Wq, Wk, Wv, Wo);

    // QKV GEMM with fused RoPE/split/fp16 epilogue
    gemm_f16<<<dim3(24, 16), 256, SMEM_F>>>(xh, wth, nullptr, 3072, DM, 0,
                                            qh, kh, vh, cosT, sinT);

    attn<<<dim3(SEQ / QPB, NH), 256>>>(anchors);

    // out = att @ Wo (plain fp32 epilogue)
    gemm_f16<<<dim3(8, 16), 256, SMEM_F>>>(ath, woth, out, DM, DM, 1,
                                           nullptr, nullptr, nullptr, nullptr, nullptr);
}

// round 12
// speedup vs baseline: 1.0607x; 1.0607x over previous
#include <cuda_runtime.h>
#include <cuda_fp16.h>
#include <cstdint>

#define SEQ 2048
#define DM 1024
#define NH 16
#define HD 64
#define NANCH 3
#define QPB 4

// ---------------- scratch ------------------------------------------------------
__device__ __half g_qh16[SEQ * DM];          // Q after RoPE, fp16 [S, H*D]
__device__ __half g_khh[NH * SEQ * HD];      // K after RoPE, fp16 [H,S,D] (128B rows)
__device__ __half g_vhh[NH * SEQ * HD];      // V fp16 [H,S,D] (128B rows)
__device__ __half g_xh[SEQ * DM];            // x fp16
__device__ __half g_wth[3072 * DM];          // [n,k] Wq|Wk|Wv^T fp16
__device__ __half g_woth[DM * DM];           // [n,k] Wo^T fp16
__device__ __half g_ath[SEQ * DM];           // attn out fp16 [S, H*D]

// ---------------- PTX helpers --------------------------------------------------
__device__ __forceinline__ uint32_t smem_u32(const void* p) {
    uint32_t a;
    asm("{ .reg .u64 t; cvta.to.shared.u64 t, %1; cvt.u32.u64 %0, t; }" : "=r"(a) : "l"(p));
    return a;
}
__device__ __forceinline__ void cp16(uint32_t s, const void* g) {
    asm volatile("cp.async.cg.shared.global [%0], [%1], 16;" :: "r"(s), "l"(g));
}
#define CP_COMMIT() asm volatile("cp.async.commit_group;" ::: "memory")
#define CP_WAIT2()  asm volatile("cp.async.wait_group 2;" ::: "memory")
#define CP_WAIT0()  asm volatile("cp.async.wait_group 0;" ::: "memory")

__device__ __forceinline__ void ldsm_x4(uint32_t& r0, uint32_t& r1, uint32_t& r2,
                                        uint32_t& r3, uint32_t a) {
    asm volatile("ldmatrix.sync.aligned.m8n8.x4.shared.b16 {%0,%1,%2,%3}, [%4];"
                 : "=r"(r0), "=r"(r1), "=r"(r2), "=r"(r3) : "r"(a));
}
__device__ __forceinline__ void mma_f16(float* d, const uint32_t* a, const uint32_t* b) {
    asm volatile(
        "mma.sync.aligned.m16n8k16.row.col.f32.f16.f16.f32 "
        "{%0,%1,%2,%3}, {%4,%5,%6,%7}, {%8,%9}, {%0,%1,%2,%3};"
        : "+f"(d[0]), "+f"(d[1]), "+f"(d[2]), "+f"(d[3])
        : "r"(a[0]), "r"(a[1]), "r"(a[2]), "r"(a[3]), "r"(b[0]), "r"(b[1]));
}

// ---------------- prep -----------------------------------------------------------
__global__ void split_x(const float* __restrict__ x) {
    int i = blockIdx.x * 256 + threadIdx.x;
    const float4 v = ((const float4*)x)[i];
    __half2* o = (__half2*)(g_xh + 4 * (size_t)i);
    o[0] = __floats2half2_rn(v.x, v.y);
    o[1] = __floats2half2_rn(v.z, v.w);
}

// W [k][n] -> Wt [n][k] fp16. z 0..2 -> Wq/Wk/Wv; z==3 -> Wo
__global__ void transpose_w(const float* __restrict__ Wq, const float* __restrict__ Wk,
                            const float* __restrict__ Wv, const float* __restrict__ Wo) {
    __shared__ float tile[32][33];
    int z = blockIdx.z;
    const float* W = (z == 0) ? Wq : (z == 1) ? Wk : (z == 2) ? Wv : Wo;
    __half* dst = (z < 3) ? (g_wth + (size_t)z * DM * DM) : g_woth;
    int k0 = blockIdx.y * 32, n0 = blockIdx.x * 32;
    int tx = threadIdx.x, ty = threadIdx.y;
    tile[ty][tx] = W[(size_t)(k0 + ty) * DM + n0 + tx];
    __syncthreads();
    dst[(size_t)(n0 + ty) * DM + k0 + tx] = __float2half(tile[tx][ty]);
}

// ---------------- fp16 GEMM: C[M,N] = A[M,K] @ B[N,K]^T --------------------------
// 128x128x64 CTA tile, 8 warps (4m x 2n), 4-stage cp.async pipeline.
#define F_BK 64
#define F_STG 32768
#define F_OFF_B 16384
#define F_NSTAGE 4

__device__ __forceinline__ uint32_t swz8(uint32_t row, uint32_t seg) {
    return row * 128 + ((seg ^ (row & 7)) << 4);
}

__device__ __forceinline__ void f16_load_chunk(
    uint32_t stage, int tid, int c, int m0, int n0, int K,
    const __half* A, const __half* B)
{
    #pragma unroll
    for (int mtx = 0; mtx < 2; mtx++) {
        const int r0 = (mtx == 0) ? m0 : n0;
        const __half* src = (mtx == 0) ? A : B;
        const uint32_t off = mtx ? F_OFF_B : 0;
        #pragma unroll
        for (int i = 0; i < 4; i++) {
            int lin = i * 256 + tid;
            int row = lin >> 3, seg = lin & 7;
            const void* g = src + (size_t)(r0 + row) * K + c * F_BK + seg * 8;
            cp16(stage + off + swz8(row, seg), g);
        }
    }
}

__global__ void __launch_bounds__(256) gemm_f16(
    const __half* __restrict__ A, const __half* __restrict__ B,
    float* __restrict__ C, int Nstride, int K, int mode,
    __half* __restrict__ Qout, __half* __restrict__ Kout, __half* __restrict__ Vout,
    const float* __restrict__ cosT, const float* __restrict__ sinT)
{
    extern __shared__ __align__(1024) char dsm[];
    const uint32_t tiles = smem_u32(dsm);

    const int tid = threadIdx.x;
    const int m0 = blockIdx.y * 128, n0 = blockIdx.x * 128;
    const int nCh = K / F_BK;

    const int w = tid >> 5, lane = tid & 31;
    const int wm = (w & 3) * 32;
    const int wn = (w >> 2) * 64;

    float acc[2][8][4];
    #pragma unroll
    for (int i = 0; i < 2; i++)
        #pragma unroll
        for (int j = 0; j < 8; j++)
            #pragma unroll
            for (int e = 0; e < 4; e++) acc[i][j][e] = 0.f;

    f16_load_chunk(tiles, tid, 0, m0, n0, K, A, B); CP_COMMIT();
    f16_load_chunk(tiles + F_STG, tid, 1, m0, n0, K, A, B); CP_COMMIT();
    f16_load_chunk(tiles + 2 * F_STG, tid, 2, m0, n0, K, A, B); CP_COMMIT();

    const int aRowL = lane & 15;
    const int aSegL = lane >> 4;
    const int bRowL = ((lane >> 4) & 1) * 8 + (lane & 7);
    const int bSegL = (lane >> 3) & 1;

    for (int c = 0; c < nCh; c++) {
        const uint32_t buf = tiles + (c % F_NSTAGE) * F_STG;
        CP_WAIT2();
        __syncthreads();
        if (c + 3 < nCh)
            f16_load_chunk(tiles + ((c + 3) % F_NSTAGE) * F_STG, tid, c + 3, m0, n0, K, A, B);
        CP_COMMIT();

        #pragma unroll
        for (int k16 = 0; k16 < 4; k16++) {
            uint32_t af[2][4], bf[4][4];
            #pragma unroll
            for (int mt = 0; mt < 2; mt++) {
                uint32_t row = wm + mt * 16 + aRowL;
                ldsm_x4(af[mt][0], af[mt][1], af[mt][2], af[mt][3],
                        buf + swz8(row, k16 * 2 + aSegL));
            }
            #pragma unroll
            for (int np = 0; np < 4; np++) {
                uint32_t row = wn + np * 16 + bRowL;
                ldsm_x4(bf[np][0], bf[np][1], bf[np][2], bf[np][3],
                        buf + F_OFF_B + swz8(row, k16 * 2 + bSegL));
            }
            #pragma unroll
            for (int mt = 0; mt < 2; mt++)
                #pragma unroll
                for (int np = 0; np < 4; np++)
                    #pragma unroll
                    for (int h = 0; h < 2; h++)
                        mma_f16(acc[mt][np * 2 + h], af[mt], &bf[np][h * 2]);
        }
        __syncthreads();
    }

    const int erow = lane >> 2, ecol = (lane & 3) * 2;

    if (mode == 0) {
        const int ncol = n0 + wn;
        const int zsel = ncol >> 10;
        const int hh = (ncol >> 6) & 15;
        #pragma unroll
        for (int mt = 0; mt < 2; mt++) {
            #pragma unroll
            for (int rsel = 0; rsel < 2; rsel++) {
                const int s = m0 + wm + mt * 16 + erow + rsel * 8;
                if (zsel == 2) {
                    __half* vb = Vout + ((size_t)hh * SEQ + s) * HD;
                    #pragma unroll
                    for (int nt = 0; nt < 8; nt++)
                        *(__half2*)(vb + nt * 8 + ecol) =
                            __floats2half2_rn(acc[mt][nt][rsel * 2], acc[mt][nt][rsel * 2 + 1]);
                } else {
                    __half* ob = (zsel == 0) ? (Qout + (size_t)s * DM + hh * HD)
                                             : (Kout + ((size_t)hh * SEQ + s) * HD);
                    #pragma unroll
                    for (int nt = 0; nt < 4; nt++) {
                        const int d0 = nt * 8 + ecol;
                        const float c0 = cosT[s * 32 + d0],     sn0 = sinT[s * 32 + d0];
                        const float c1 = cosT[s * 32 + d0 + 1], sn1 = sinT[s * 32 + d0 + 1];
                        const float a0 = acc[mt][nt][rsel * 2],     a1 = acc[mt][nt][rsel * 2 + 1];
                        const float b0 = acc[mt][nt + 4][rsel * 2], b1 = acc[mt][nt + 4][rsel * 2 + 1];
                        *(__half2*)(ob + d0) =
                            __floats2half2_rn(a0 * c0 - b0 * sn0, a1 * c1 - b1 * sn1);
                        *(__half2*)(ob + d0 + 32) =
                            __floats2half2_rn(b0 * c0 + a0 * sn0, b1 * c1 + a1 * sn1);
                    }
                }
            }
        }
    } else {
        #pragma unroll
        for (int mt = 0; mt < 2; mt++)
            #pragma unroll
            for (int nt = 0; nt < 8; nt++) {
                const float* d = acc[mt][nt];
                size_t r = (size_t)(m0 + wm + mt * 16 + erow);
                size_t col = n0 + wn + nt * 8 + ecol;
                *(float2*)&C[r * Nstride + col]       = make_float2(d[0], d[1]);
                *(float2*)&C[(r + 8) * Nstride + col] = make_float2(d[2], d[3]);
            }
    }
}

// ---------------- sparse attention: 4 queries / 256-thread block ----------------
// Logits via mma.sync; K staging with compile-time tile addressing.
__global__ void __launch_bounds__(256) attn(const int* __restrict__ anchors) {
    const int h = blockIdx.y;
    const int tid = threadIdx.x;
    const int ql = tid >> 6;
    const int j = tid & 63;
    const int s = blockIdx.x * QPB + ql;
    const int wq = (tid >> 5) & 1;           // warp within query
    const int lane = tid & 31;

    __shared__ __align__(16) char sK[QPB][4 * 2048];   // 4 tiles x 16 rows x 128B
    __shared__ __half2 sqh[QPB][32];                   // q as half2
    __shared__ float2 sWO[QPB][64];                    // (weight, byteoff-as-float)
    __shared__ int stile[QPB][4];
    __shared__ float wred[QPB][2][2];
    __shared__ float spart[QPB][2][64];

    // q (half2) and tile indices
    if (j < 32)
        sqh[ql][j] = ((const __half2*)(g_qh16 + (size_t)s * DM + h * HD))[j];
    if (j < 4)
        stile[ql][j] = (j < NANCH) ? anchors[(h * SEQ + s) * NANCH + j] : (s >> 4);
    __syncthreads();

    const int t0 = stile[ql][0], t1 = stile[ql][1];
    const int t2 = stile[ql][2], t3 = stile[ql][3];

    // stage 4 K tiles (2KB each, contiguous) with invariant per-thread offsets
    {
        const uint32_t sbase = smem_u32(sK[ql]);
        const char* hb = (const char*)g_khh + (size_t)h * SEQ * 128;
        const uint32_t so = (j >> 3) * 128 + (((j & 7) ^ (j >> 3)) << 4);
        const uint32_t go = j * 16;
        const char* p0 = hb + t0 * 2048 + go;
        const char* p1 = hb + t1 * 2048 + go;
        const char* p2 = hb + t2 * 2048 + go;
        const char* p3 = hb + t3 * 2048 + go;
        cp16(sbase + so,               p0);
        cp16(sbase + 1024 + so,        p0 + 1024);
        cp16(sbase + 2048 + so,        p1);
        cp16(sbase + 3072 + so,        p1 + 1024);
        cp16(sbase + 4096 + so,        p2);
        cp16(sbase + 5120 + so,        p2 + 1024);
        cp16(sbase + 6144 + so,        p3);
        cp16(sbase + 7168 + so,        p3 + 1024);
    }
    CP_COMMIT();
    CP_WAIT0();
    __syncthreads();

    // B fragments: q replicated across all 8 n-columns
    uint32_t bq[4][2];
    #pragma unroll
    for (int c = 0; c < 4; c++) {
        bq[c][0] = *(const uint32_t*)&sqh[ql][c * 8 + (lane & 3)];
        bq[c][1] = *(const uint32_t*)&sqh[ql][c * 8 + (lane & 3) + 4];
    }

    // logits via mma: 2 m-tiles of 16 keys, 4 k-chunks each
    const uint32_t sKb = smem_u32(sK[ql]);
    float lg[4];                             // keys: wq*32 + {r, r+8, 16+r, 24+r}
    #pragma unroll
    for (int t = 0; t < 2; t++) {
        float c4[4] = {0.f, 0.f, 0.f, 0.f};
        #pragma unroll
        for (int c = 0; c < 4; c++) {
            uint32_t a[4];
            ldsm_x4(a[0], a[1], a[2], a[3],
                    sKb + swz8(wq * 32 + t * 16 + (lane & 15), c * 2 + (lane >> 4)));
            mma_f16(c4, a, bq[c]);
        }
        lg[t * 2]     = c4[0] * 0.125f;      // key row r
        lg[t * 2 + 1] = c4[2] * 0.125f;      // key row r+8
    }

    const int r = lane >> 2;
    const int ti0 = wq ? t2 : t0, ti1 = wq ? t3 : t1;
    int kid[4] = {ti0 * 16 + r, ti0 * 16 + r + 8, ti1 * 16 + r, ti1 * 16 + r + 8};
    bool msk[4];
    #pragma unroll
    for (int i = 0; i < 4; i++) {
        msk[i] = kid[i] > s;
        if (msk[i]) lg[i] = -1e30f;
    }

    // softmax (each key duplicated x4 across the quad -> sum scaled by 0.25)
    float m = fmaxf(fmaxf(lg[0], lg[1]), fmaxf(lg[2], lg[3]));
    #pragma unroll
    for (int off = 16; off; off >>= 1) m = fmaxf(m, __shfl_xor_sync(~0u, m, off));
    if (lane == 0) wred[ql][0][wq] = m;
    __syncthreads();
    m = fmaxf(wred[ql][0][0], wred[ql][0][1]);

    float e[4];
    float lsum = 0.f;
    #pragma unroll
    for (int i = 0; i < 4; i++) {
        e[i] = msk[i] ? 0.f : __expf(lg[i] - m);
        lsum += e[i];
    }
    #pragma unroll
    for (int off = 16; off; off >>= 1) lsum += __shfl_xor_sync(~0u, lsum, off);
    if (lane == 0) wred[ql][1][wq] = lsum;
    __syncthreads();
    const float ssum = (wred[ql][1][0] + wred[ql][1][1]) * 0.25f;
    const float inv = 1.0f / ssum;

    // quad leaders publish (weight, V byte offset) for their 4 keys
    if ((lane & 3) == 0) {
        sWO[ql][wq * 32 + r]      = make_float2(e[0] * inv, __int_as_float(kid[0] << 7));
        sWO[ql][wq * 32 + r + 8]  = make_float2(e[1] * inv, __int_as_float(kid[1] << 7));
        sWO[ql][wq * 32 + r + 16] = make_float2(e[2] * inv, __int_as_float(kid[2] << 7));
        sWO[ql][wq * 32 + r + 24] = make_float2(e[3] * inv, __int_as_float(kid[3] << 7));
    }
    __syncwarp();

    // V phase: 2 keys per iteration; lanes 0-15 even key, 16-31 odd key.
    {
        const char* vb = (const char*)g_vhh + (size_t)h * SEQ * 128 + 8 * (lane & 15);
        const int sel = lane >> 4;           // 0 or 1
        float4 acc = make_float4(0.f, 0.f, 0.f, 0.f);
        #pragma unroll
        for (int i = 0; i < 16; i++) {
            const float2 wo = sWO[ql][wq * 32 + 2 * i + sel];
            const float wgt = wo.x;
            const __half2* vp = (const __half2*)(vb + __float_as_int(wo.y));
            const float2 v0 = __half22float2(vp[0]);
            const float2 v1 = __half22float2(vp[1]);
            acc.x = fmaf(wgt, v0.x, acc.x);
            acc.y = fmaf(wgt, v0.y, acc.y);
            acc.z = fmaf(wgt, v1.x, acc.z);
            acc.w = fmaf(wgt, v1.y, acc.w);
        }
        acc.x += __shfl_xor_sync(~0u, acc.x, 16);
        acc.y += __shfl_xor_sync(~0u, acc.y, 16);
        acc.z += __shfl_xor_sync(~0u, acc.z, 16);
        acc.w += __shfl_xor_sync(~0u, acc.w, 16);
        if (lane < 16)
            ((float4*)spart[ql][wq])[lane] = acc;
    }
    __syncthreads();

    g_ath[(size_t)s * DM + h * HD + j] =
        __float2half(spart[ql][0][j] + spart[ql][1][j]);
}

// ---------------- launch ---------------------------------------------------------
extern "C" void kernel_launch(void* const* d_in, const int* in_sizes, int n_in,
                              void* d_out, int out_size)
{
    const float* x    = (const float*)d_in[0];
    const float* Wq   = (const float*)d_in[1];
    const float* Wk   = (const float*)d_in[2];
    const float* Wv   = (const float*)d_in[3];
    const float* Wo   = (const float*)d_in[4];
    const float* cosT = (const float*)d_in[5];
    const float* sinT = (const float*)d_in[6];
    const int* anchors = (const int*)d_in[7];
    float* out = (float*)d_out;

    const int SMEM_F = F_NSTAGE * F_STG;   // 128 KB
    cudaFuncSetAttribute(gemm_f16, cudaFuncAttributeMaxDynamicSharedMemorySize, SMEM_F);

    __half *xh = nullptr, *wth = nullptr, *woth = nullptr, *ath = nullptr;
    __half *qh = nullptr, *kh = nullptr, *vh = nullptr;
    cudaGetSymbolAddress((void**)&xh, g_xh);
    cudaGetSymbolAddress((void**)&wth, g_wth);
    cudaGetSymbolAddress((void**)&woth, g_woth);
    cudaGetSymbolAddress((void**)&ath, g_ath);
    cudaGetSymbolAddress((void**)&qh, g_qh16);
    cudaGetSymbolAddress((void**)&kh, g_khh);
    cudaGetSymbolAddress((void**)&vh, g_vhh);

    split_x<<<(SEQ * DM / 4) / 256, 256>>>(x);
    transpose_w<<<dim3(32, 32, 4), dim3(32, 32)>>>(Wq, Wk, Wv, Wo);

    // QKV GEMM with fused RoPE/split/fp16 epilogue
    gemm_f16<<<dim3(24, 16), 256, SMEM_F>>>(xh, wth, nullptr, 3072, DM, 0,
                                            qh, kh, vh, cosT, sinT);

    attn<<<dim3(SEQ / QPB, NH), 256>>>(anchors);

    // out = att @ Wo (plain fp32 epilogue)
    gemm_f16<<<dim3(8, 16), 256, SMEM_F>>>(ath, woth, out, DM, DM, 1,
                                           nullptr, nullptr, nullptr, nullptr, nullptr);
}